// round 4
// baseline (speedup 1.0000x reference)
#include <cuda_runtime.h>
#include <cstdint>

#define N_NODES 500000
#define N_EDGES 16000000
#define IN_DIM 17

// Packed accumulator per node: bits[16:64) = fixed-point(2^-32) sum of messages,
// bits[0:16) = edge count. One u64 RED per edge instead of a v2.f32 (2 f32 RMWs).
__device__ unsigned long long g_acc[N_NODES];
__device__ float g_proj[N_NODES];   // x . w_l
__device__ float g_base[N_NODES];   // b_l + x . w_r

#define FIX_SCALE 4294967296.0f     // 2^32
#define INV_FIX_SCALE 2.3283064365386963e-10f

// ---------------------------------------------------------------------------
// Kernel 1: per-node projection + accumulator zeroing.
// float4 coalesced stage into smem, then per-row dot products from smem
// (stride 17 is odd -> conflict-free bank permutation).
// ---------------------------------------------------------------------------
__global__ void __launch_bounds__(256) node_prep(
    const float* __restrict__ x,
    const float* __restrict__ w_l,
    const float* __restrict__ b_l,
    const float* __restrict__ w_r)
{
    __shared__ float sx[256 * IN_DIM];
    __shared__ float swl[IN_DIM], swr[IN_DIM];

    int base = blockIdx.x * 256;
    int nblk = N_NODES - base; if (nblk > 256) nblk = 256;

    if (threadIdx.x < IN_DIM) {
        swl[threadIdx.x] = w_l[threadIdx.x];
        swr[threadIdx.x] = w_r[threadIdx.x];
    }

    const float* xb = x + (size_t)base * IN_DIM;
    if (nblk == 256) {
        // 256*17 floats = 1088 float4, tile start is 16B-aligned (17408*blockIdx).
        const float4* x4 = (const float4*)xb;
        float4* s4 = (float4*)sx;
#pragma unroll
        for (int i = threadIdx.x; i < (256 * IN_DIM) / 4; i += 256)
            s4[i] = __ldg(&x4[i]);
    } else {
        for (int i = threadIdx.x; i < nblk * IN_DIM; i += 256)
            sx[i] = xb[i];
    }
    __syncthreads();

    int n = base + threadIdx.x;
    if (threadIdx.x >= nblk) return;

    const float* row = sx + threadIdx.x * IN_DIM;
    float pl = 0.f, pr = 0.f;
#pragma unroll
    for (int i = 0; i < IN_DIM; i++) {
        float v = row[i];
        pl = fmaf(v, swl[i], pl);
        pr = fmaf(v, swr[i], pr);
    }
    g_proj[n] = pl;
    g_base[n] = pr + __ldg(b_l);
    g_acc[n]  = 0ull;
}

// ---------------------------------------------------------------------------
// Kernel 2: edge scatter. 8 edges per thread (2x int4 per side, __ldcs so the
// 128 MB index stream is evict-first in L2, protecting proj/acc residency).
// One red.global.add.u64 per edge.
// ---------------------------------------------------------------------------
__device__ __forceinline__ void red_edge(int dst, float m)
{
    // Low 16 bits of the shifted sum are zero -> OR is an exact +1 on count.
    long long pkt = ((long long)llrintf(m * FIX_SCALE) << 16) | 1ll;
    asm volatile("red.global.add.u64 [%0], %1;"
                 :: "l"(&g_acc[dst]), "l"(pkt) : "memory");
}

__global__ void __launch_bounds__(256) edge_scatter(const int* __restrict__ ei)
{
    const int4* __restrict__ srcv = (const int4*)ei;
    const int4* __restrict__ dstv = (const int4*)(ei + N_EDGES);
    int i = blockIdx.x * blockDim.x + threadIdx.x;
    if (i >= N_EDGES / 8) return;

    int4 s0 = __ldcs(&srcv[2 * i]);
    int4 s1 = __ldcs(&srcv[2 * i + 1]);
    int4 d0 = __ldcs(&dstv[2 * i]);
    int4 d1 = __ldcs(&dstv[2 * i + 1]);

    float m0 = __ldg(&g_proj[s0.x]);
    float m1 = __ldg(&g_proj[s0.y]);
    float m2 = __ldg(&g_proj[s0.z]);
    float m3 = __ldg(&g_proj[s0.w]);
    float m4 = __ldg(&g_proj[s1.x]);
    float m5 = __ldg(&g_proj[s1.y]);
    float m6 = __ldg(&g_proj[s1.z]);
    float m7 = __ldg(&g_proj[s1.w]);

    red_edge(d0.x, m0); red_edge(d0.y, m1);
    red_edge(d0.z, m2); red_edge(d0.w, m3);
    red_edge(d1.x, m4); red_edge(d1.y, m5);
    red_edge(d1.z, m6); red_edge(d1.w, m7);
}

// ---------------------------------------------------------------------------
// Kernel 3: finalize. decode packed acc -> mean -> +base -> elu -> out linear.
// ---------------------------------------------------------------------------
__global__ void __launch_bounds__(256) finalize(
    float* __restrict__ out,
    const float* __restrict__ w_o,
    const float* __restrict__ b_o)
{
    int n = blockIdx.x * blockDim.x + threadIdx.x;
    if (n >= N_NODES) return;
    long long p = (long long)g_acc[n];
    int cnt = (int)(p & 0xFFFFll);
    float sum = (float)((p - (long long)cnt) >> 16) * INV_FIX_SCALE;
    float mean = sum / fmaxf((float)cnt, 1.0f);
    float h = mean + g_base[n];
    h = (h > 0.f) ? h : expm1f(h);          // elu, alpha=1
    out[n] = fmaf(h, __ldg(w_o), __ldg(b_o));
}

extern "C" void kernel_launch(void* const* d_in, const int* in_sizes, int n_in,
                              void* d_out, int out_size)
{
    const float* x    = (const float*)d_in[0];
    const int*   ei   = (const int*)d_in[1];
    // d_in[2] = edge_weight: unused (faithful to reference / PyG SAGEConv)
    const float* w_l  = (const float*)d_in[3];
    const float* b_l  = (const float*)d_in[4];
    const float* w_r  = (const float*)d_in[5];
    const float* w_o  = (const float*)d_in[6];
    const float* b_o  = (const float*)d_in[7];
    float*       out  = (float*)d_out;

    (void)in_sizes; (void)n_in; (void)out_size;

    const int T = 256;
    node_prep<<<(N_NODES + T - 1) / T, T>>>(x, w_l, b_l, w_r);
    edge_scatter<<<(N_EDGES / 8 + T - 1) / T, T>>>(ei);
    finalize<<<(N_NODES + T - 1) / T, T>>>(out, w_o, b_o);
}